// round 9
// baseline (speedup 1.0000x reference)
#include <cuda_runtime.h>
#include <cuda_fp16.h>

#define L_TOTAL 32768
#define KQ      1024
#define EDIM    64
#define MT      64             // latents per CTA (2 tile-pairs x 32)
#define KQUARTER 256           // codes per k-split quarter
#define CHK     16             // codes per staged chunk per quarter
#define NCHUNK  (KQUARTER / CHK)  // 16
#define SROW    72             // padded smem row stride (halves)
#define THREADS 256

// scratch tables (no cudaMalloc allowed)
__device__ float  g_c[KQ];             // ||e_k||^2 (fp32)
__device__ __half g_ehi[KQ * EDIM];    // fp16-rounded embeddings [k][e]
__device__ __half g_elo[KQ * EDIM];    // residual

__device__ __forceinline__ void mma16816(float* d, const unsigned* a,
                                         unsigned b0, unsigned b1) {
    asm volatile(
        "mma.sync.aligned.m16n8k16.row.col.f32.f16.f16.f32 "
        "{%0,%1,%2,%3}, {%4,%5,%6,%7}, {%8,%9}, {%0,%1,%2,%3};"
        : "+f"(d[0]), "+f"(d[1]), "+f"(d[2]), "+f"(d[3])
        : "r"(a[0]), "r"(a[1]), "r"(a[2]), "r"(a[3]), "r"(b0), "r"(b1));
}

__device__ __forceinline__ unsigned packsplit(float a, float b, unsigned& lo) {
    __half ha = __float2half_rn(a), hb = __float2half_rn(b);
    float la = a - __half2float(ha), lb = b - __half2float(hb);
    __half2 H = __halves2half2(ha, hb);
    __half2 L = __halves2half2(__float2half_rn(la), __float2half_rn(lb));
    lo = *reinterpret_cast<unsigned*>(&L);
    return *reinterpret_cast<unsigned*>(&H);
}

__device__ __forceinline__ void cp16(void* dst_smem, const void* src) {
    unsigned d = (unsigned)__cvta_generic_to_shared(dst_smem);
    asm volatile("cp.async.cg.shared.global [%0], [%1], 16;"
                 :: "r"(d), "l"(src) : "memory");
}

// Parallel prep: 8 threads per code row. ||e||^2 via 8-lane shfl tree.
__global__ void vq_prep_kernel(const float* __restrict__ emb) {
    int t   = blockIdx.x * blockDim.x + threadIdx.x;  // 0..8191
    int k   = t >> 3;
    int seg = t & 7;
    const float4* p = reinterpret_cast<const float4*>(emb + k * EDIM + seg * 8);
    float4 v0 = p[0], v1 = p[1];
    float s = v0.x * v0.x + v0.y * v0.y + v0.z * v0.z + v0.w * v0.w
            + v1.x * v1.x + v1.y * v1.y + v1.z * v1.z + v1.w * v1.w;
    uint4 H, L;
    H.x = packsplit(v0.x, v0.y, L.x);
    H.y = packsplit(v0.z, v0.w, L.y);
    H.z = packsplit(v1.x, v1.y, L.z);
    H.w = packsplit(v1.z, v1.w, L.w);
    *reinterpret_cast<uint4*>(&g_ehi[k * EDIM + seg * 8]) = H;
    *reinterpret_cast<uint4*>(&g_elo[k * EDIM + seg * 8]) = L;
    s += __shfl_xor_sync(0xffffffffu, s, 1);
    s += __shfl_xor_sync(0xffffffffu, s, 2);
    s += __shfl_xor_sync(0xffffffffu, s, 4);
    if (seg == 0) g_c[k] = s;
}

struct Top2 { float b1, b2; int i1, i2; };

__device__ __forceinline__ void upd(Top2& t, float s, int c) {
    if (s < t.b1)      { t.b2 = t.b1; t.i2 = t.i1; t.b1 = s; t.i1 = c; }
    else if (s < t.b2) { t.b2 = s; t.i2 = c; }
}

__global__ void __launch_bounds__(THREADS)
vq_mma_kernel(const float* __restrict__ x,
              const float* __restrict__ emb,
              float* __restrict__ out) {
    // [buf][quarter][tab(hi/lo)] double-buffered code chunks
    __shared__ __align__(16) __half sB[2][4][2][CHK * SROW];
    __shared__ float cs[KQ];
    __shared__ float mb1[4][MT], mb2[4][MT];
    __shared__ int   mi1[4][MT], mi2[4][MT];
    __shared__ int   sidx[MT];

    const int tid   = threadIdx.x;
    const int warp  = tid >> 5;
    const int lane  = tid & 31;
    const int g     = lane >> 2;       // row within m16 tile
    const int T     = lane & 3;        // thread in quad
    const int tp    = warp & 1;        // tile-pair (latents tp*32..tp*32+31)
    const int q     = warp >> 1;       // k-quarter (codes q*256..q*256+255)
    const int lbase = blockIdx.x * MT;

    // stage ||e||^2
    #pragma unroll
    for (int i = 0; i < KQ / THREADS; i++)
        cs[tid + i * THREADS] = g_c[tid + i * THREADS];

    // Stage chunk ch into buffer buf: all 4 quarters, hi+lo. 1024 cp16.
    auto stage = [&](int ch, int buf) {
        #pragma unroll
        for (int i = 0; i < 4; i++) {
            int u   = tid + i * THREADS;      // 0..1023
            int seg = u & 7;
            int row = (u >> 3) & 15;
            int tab = (u >> 7) & 1;
            int qq  = u >> 8;
            const __half* src = tab ? g_elo : g_ehi;
            cp16(&sB[buf][qq][tab][row * SROW + seg * 8],
                 &src[(size_t)(qq * KQUARTER + ch * CHK + row) * EDIM + seg * 8]);
        }
        asm volatile("cp.async.commit_group;" ::: "memory");
    };

    stage(0, 0);

    // A fragments for TWO tiles: tile tt rows = lbase + tp*32 + tt*16 + {g, g+8}
    unsigned ahi[2][4][4], alo[2][4][4];
    #pragma unroll
    for (int tt = 0; tt < 2; tt++) {
        const float* xr0 = x + (size_t)(lbase + tp * 32 + tt * 16 + g) * EDIM;
        const float* xr1 = xr0 + 8 * EDIM;
        #pragma unroll
        for (int ks = 0; ks < 4; ks++) {
            int c0 = 16 * ks + 2 * T;
            float2 v;
            v = *reinterpret_cast<const float2*>(xr0 + c0);
            ahi[tt][ks][0] = packsplit(-2.f * v.x, -2.f * v.y, alo[tt][ks][0]);
            v = *reinterpret_cast<const float2*>(xr1 + c0);
            ahi[tt][ks][1] = packsplit(-2.f * v.x, -2.f * v.y, alo[tt][ks][1]);
            v = *reinterpret_cast<const float2*>(xr0 + c0 + 8);
            ahi[tt][ks][2] = packsplit(-2.f * v.x, -2.f * v.y, alo[tt][ks][2]);
            v = *reinterpret_cast<const float2*>(xr1 + c0 + 8);
            ahi[tt][ks][3] = packsplit(-2.f * v.x, -2.f * v.y, alo[tt][ks][3]);
        }
    }

    Top2 tp2[2][2];
    #pragma unroll
    for (int a = 0; a < 2; a++)
        #pragma unroll
        for (int b = 0; b < 2; b++) {
            tp2[a][b].b1 = tp2[a][b].b2 = 3.4e38f;
            tp2[a][b].i1 = tp2[a][b].i2 = 0;
        }

    asm volatile("cp.async.wait_group 0;" ::: "memory");
    __syncthreads();

    int buf = 0;
    #pragma unroll 1
    for (int ch = 0; ch < NCHUNK; ch++) {
        if (ch + 1 < NCHUNK) stage(ch + 1, buf ^ 1);   // overlap next stage

        float dhh[2][2][4] = {};   // [tile][j][4]
        float dhl[2][2][4] = {};
        float dlh[2][2][4] = {};

        #pragma unroll
        for (int j = 0; j < 2; j++) {
            const int nrow = 8 * j + g;
            const __half* ph = &sB[buf][q][0][nrow * SROW + 2 * T];
            const __half* pl = &sB[buf][q][1][nrow * SROW + 2 * T];
            #pragma unroll
            for (int kh = 0; kh < 2; kh++) {
                int off = kh * 32;
                unsigned h0 = *reinterpret_cast<const unsigned*>(ph + off);
                unsigned h1 = *reinterpret_cast<const unsigned*>(ph + off + 8);
                unsigned h2 = *reinterpret_cast<const unsigned*>(ph + off + 16);
                unsigned h3 = *reinterpret_cast<const unsigned*>(ph + off + 24);
                unsigned l0 = *reinterpret_cast<const unsigned*>(pl + off);
                unsigned l1 = *reinterpret_cast<const unsigned*>(pl + off + 8);
                unsigned l2 = *reinterpret_cast<const unsigned*>(pl + off + 16);
                unsigned l3 = *reinterpret_cast<const unsigned*>(pl + off + 24);
                int ks = 2 * kh;
                // B fragments reused for both A tiles (12 MMA per 8 LDS)
                mma16816(dhh[0][j], ahi[0][ks], h0, h1);
                mma16816(dhh[1][j], ahi[1][ks], h0, h1);
                mma16816(dhl[0][j], ahi[0][ks], l0, l1);
                mma16816(dhl[1][j], ahi[1][ks], l0, l1);
                mma16816(dlh[0][j], alo[0][ks], h0, h1);
                mma16816(dlh[1][j], alo[1][ks], h0, h1);
                mma16816(dhh[0][j], ahi[0][ks + 1], h2, h3);
                mma16816(dhh[1][j], ahi[1][ks + 1], h2, h3);
                mma16816(dhl[0][j], ahi[0][ks + 1], l2, l3);
                mma16816(dhl[1][j], ahi[1][ks + 1], l2, l3);
                mma16816(dlh[0][j], alo[0][ks + 1], h2, h3);
                mma16816(dlh[1][j], alo[1][ks + 1], h2, h3);
            }
        }

        const int cb = q * KQUARTER + ch * CHK;
        #pragma unroll
        for (int tt = 0; tt < 2; tt++) {
            #pragma unroll
            for (int j = 0; j < 2; j++) {
                int col = cb + 8 * j + 2 * T;
                float e0 = cs[col], e1 = cs[col + 1];
                upd(tp2[tt][0], e0 + (dhh[tt][j][0] + dhl[tt][j][0] + dlh[tt][j][0]), col);
                upd(tp2[tt][0], e1 + (dhh[tt][j][1] + dhl[tt][j][1] + dlh[tt][j][1]), col + 1);
                upd(tp2[tt][1], e0 + (dhh[tt][j][2] + dhl[tt][j][2] + dlh[tt][j][2]), col);
                upd(tp2[tt][1], e1 + (dhh[tt][j][3] + dhl[tt][j][3] + dlh[tt][j][3]), col + 1);
            }
        }

        asm volatile("cp.async.wait_group 0;" ::: "memory");
        __syncthreads();
        buf ^= 1;
    }

    // Reduce across the 4 lanes of each quad (xor 1, 2 stay in-quad).
    #pragma unroll
    for (int tt = 0; tt < 2; tt++) {
        #pragma unroll
        for (int s = 0; s < 2; s++) {
            Top2& t = tp2[tt][s];
            #pragma unroll
            for (int m = 1; m < 4; m <<= 1) {
                float ob1 = __shfl_xor_sync(0xffffffffu, t.b1, m);
                float ob2 = __shfl_xor_sync(0xffffffffu, t.b2, m);
                int   oi1 = __shfl_xor_sync(0xffffffffu, t.i1, m);
                int   oi2 = __shfl_xor_sync(0xffffffffu, t.i2, m);
                bool of = (ob1 < t.b1) || (ob1 == t.b1 && oi1 < t.i1);
                if (of) {
                    bool t2 = (t.b1 < ob2) || (t.b1 == ob2 && t.i1 < oi2);
                    t.b2 = t2 ? t.b1 : ob2;
                    t.i2 = t2 ? t.i1 : oi2;
                    t.b1 = ob1; t.i1 = oi1;
                } else {
                    bool t2 = (ob1 < t.b2) || (ob1 == t.b2 && oi1 < t.i2);
                    if (t2) { t.b2 = ob1; t.i2 = oi1; }
                }
            }
        }
    }

    // Publish all quarters' top2, then quarter-0 warps merge in ascending-k
    // order (strict < keeps first-min semantics).
    if (T == 0) {
        #pragma unroll
        for (int tt = 0; tt < 2; tt++)
            #pragma unroll
            for (int s = 0; s < 2; s++) {
                int lr = tp * 32 + tt * 16 + g + 8 * s;
                mb1[q][lr] = tp2[tt][s].b1; mi1[q][lr] = tp2[tt][s].i1;
                mb2[q][lr] = tp2[tt][s].b2; mi2[q][lr] = tp2[tt][s].i2;
            }
    }
    __syncthreads();

    if (q == 0 && T == 0) {
        #pragma unroll
        for (int tt = 0; tt < 2; tt++) {
            #pragma unroll
            for (int s = 0; s < 2; s++) {
                int lr = tp * 32 + tt * 16 + g + 8 * s;
                Top2& t = tp2[tt][s];
                #pragma unroll
                for (int qq = 1; qq < 4; qq++) {
                    float ob1 = mb1[qq][lr], ob2 = mb2[qq][lr];
                    int   oi1 = mi1[qq][lr], oi2 = mi2[qq][lr];
                    if (ob1 < t.b1) {
                        bool t2 = (t.b1 <= ob2);
                        t.b2 = t2 ? t.b1 : ob2;
                        t.i2 = t2 ? t.i1 : oi2;
                        t.b1 = ob1; t.i1 = oi1;
                    } else if (ob1 < t.b2) {
                        t.b2 = ob1; t.i2 = oi1;
                    }
                }

                int win = t.i1;
                if (t.b2 - t.b1 < 5e-3f) {
                    // exact fp32 recheck of the two candidates
                    const float* xr  = x   + (size_t)(lbase + lr) * EDIM;
                    const float* e1r = emb + (size_t)t.i1 * EDIM;
                    const float* e2r = emb + (size_t)t.i2 * EDIM;
                    float d1 = 0.f, d2 = 0.f;
                    #pragma unroll 8
                    for (int e = 0; e < EDIM; e++) {
                        float xv = xr[e];
                        d1 = fmaf(xv, e1r[e], d1);
                        d2 = fmaf(xv, e2r[e], d2);
                    }
                    float s1 = fmaf(-2.f, d1, cs[t.i1]);
                    float s2 = fmaf(-2.f, d2, cs[t.i2]);
                    if (s2 < s1 || (s2 == s1 && t.i2 < t.i1)) win = t.i2;
                }
                sidx[lr] = win;
            }
        }
    }
    __syncthreads();

    // Coalesced epilogue: out = [x | quantized | z_hat | indices], fp32.
    const size_t LE4 = (size_t)L_TOTAL * (EDIM / 4);
    const float4* x4  = reinterpret_cast<const float4*>(x);
    const float4* e4p = reinterpret_cast<const float4*>(emb);
    float4* out4 = reinterpret_cast<float4*>(out);
    #pragma unroll
    for (int i = 0; i < (MT * EDIM / 4) / THREADS; i++) {
        int idx = tid + i * THREADS;
        int l = idx >> 4, c4 = idx & 15;
        size_t goff = (size_t)(lbase + l) * 16 + c4;
        float4 xv = x4[goff];
        float4 qv = e4p[(size_t)sidx[l] * 16 + c4];
        out4[goff] = xv;
        out4[LE4 + goff] = qv;
        float4 zh;
        zh.x = (xv.x + qv.x) - xv.x;
        zh.y = (xv.y + qv.y) - xv.y;
        zh.z = (xv.z + qv.z) - xv.z;
        zh.w = (xv.w + qv.w) - xv.w;
        out4[2 * LE4 + goff] = zh;
    }
    if (tid < MT)
        out[3 * (size_t)L_TOTAL * EDIM + lbase + tid] = (float)sidx[tid];
}

extern "C" void kernel_launch(void* const* d_in, const int* in_sizes, int n_in,
                              void* d_out, int out_size) {
    const float* x   = (const float*)d_in[0];
    const float* emb = (const float*)d_in[1];
    float* out       = (float*)d_out;

    vq_prep_kernel<<<64, 128>>>(emb);
    vq_mma_kernel<<<L_TOTAL / MT, THREADS>>>(x, emb, out);
}

// round 10
// speedup vs baseline: 1.5939x; 1.5939x over previous
#include <cuda_runtime.h>
#include <cuda_fp16.h>

#define L_TOTAL 32768
#define KQ      1024
#define EDIM    64
#define MT      64             // latents per CTA (4 tiles x 16)
#define KHALF   512            // codes per k-split half
#define CHK     32             // codes per staged chunk per half
#define NCHUNK  (KHALF / CHK)  // 16
#define SROW    72             // padded smem row stride (halves) -> conflict-free
#define THREADS 256

// scratch tables (no cudaMalloc allowed)
__device__ float  g_c[KQ];             // ||e_k||^2 (fp32)
__device__ __half g_ehi[KQ * EDIM];    // fp16-rounded embeddings [k][e]
__device__ __half g_elo[KQ * EDIM];    // residual

__device__ __forceinline__ void mma16816(float* d, const unsigned* a,
                                         unsigned b0, unsigned b1) {
    asm volatile(
        "mma.sync.aligned.m16n8k16.row.col.f32.f16.f16.f32 "
        "{%0,%1,%2,%3}, {%4,%5,%6,%7}, {%8,%9}, {%0,%1,%2,%3};"
        : "+f"(d[0]), "+f"(d[1]), "+f"(d[2]), "+f"(d[3])
        : "r"(a[0]), "r"(a[1]), "r"(a[2]), "r"(a[3]), "r"(b0), "r"(b1));
}

__device__ __forceinline__ void ldsm4(unsigned& r0, unsigned& r1,
                                      unsigned& r2, unsigned& r3,
                                      unsigned addr) {
    asm volatile("ldmatrix.sync.aligned.m8n8.x4.shared.b16 {%0,%1,%2,%3}, [%4];"
                 : "=r"(r0), "=r"(r1), "=r"(r2), "=r"(r3) : "r"(addr));
}

__device__ __forceinline__ unsigned packsplit(float a, float b, unsigned& lo) {
    __half ha = __float2half_rn(a), hb = __float2half_rn(b);
    float la = a - __half2float(ha), lb = b - __half2float(hb);
    __half2 H = __halves2half2(ha, hb);
    __half2 L = __halves2half2(__float2half_rn(la), __float2half_rn(lb));
    lo = *reinterpret_cast<unsigned*>(&L);
    return *reinterpret_cast<unsigned*>(&H);
}

__device__ __forceinline__ void cp16(void* dst_smem, const void* src) {
    unsigned d = (unsigned)__cvta_generic_to_shared(dst_smem);
    asm volatile("cp.async.cg.shared.global [%0], [%1], 16;"
                 :: "r"(d), "l"(src) : "memory");
}

// Parallel prep: 8 threads per code row. ||e||^2 via 8-lane shfl tree.
__global__ void vq_prep_kernel(const float* __restrict__ emb) {
    int t   = blockIdx.x * blockDim.x + threadIdx.x;  // 0..8191
    int k   = t >> 3;
    int seg = t & 7;
    const float4* p = reinterpret_cast<const float4*>(emb + k * EDIM + seg * 8);
    float4 v0 = p[0], v1 = p[1];
    float s = v0.x * v0.x + v0.y * v0.y + v0.z * v0.z + v0.w * v0.w
            + v1.x * v1.x + v1.y * v1.y + v1.z * v1.z + v1.w * v1.w;
    uint4 H, L;
    H.x = packsplit(v0.x, v0.y, L.x);
    H.y = packsplit(v0.z, v0.w, L.y);
    H.z = packsplit(v1.x, v1.y, L.z);
    H.w = packsplit(v1.z, v1.w, L.w);
    *reinterpret_cast<uint4*>(&g_ehi[k * EDIM + seg * 8]) = H;
    *reinterpret_cast<uint4*>(&g_elo[k * EDIM + seg * 8]) = L;
    s += __shfl_xor_sync(0xffffffffu, s, 1);
    s += __shfl_xor_sync(0xffffffffu, s, 2);
    s += __shfl_xor_sync(0xffffffffu, s, 4);
    if (seg == 0) g_c[k] = s;
}

struct Top2 { float b1, b2; int i1, i2; };

__device__ __forceinline__ void upd(Top2& t, float s, int c) {
    if (s < t.b1)      { t.b2 = t.b1; t.i2 = t.i1; t.b1 = s; t.i1 = c; }
    else if (s < t.b2) { t.b2 = s; t.i2 = c; }
}

__global__ void __launch_bounds__(THREADS)
vq_mma_kernel(const float* __restrict__ x,
              const float* __restrict__ emb,
              float* __restrict__ out) {
    // [buf][half][tab(hi/lo)] double-buffered code chunks
    __shared__ __align__(16) __half sB[2][2][2][CHK * SROW];
    __shared__ float cs[KQ];
    __shared__ float mb1[MT], mb2[MT];
    __shared__ int   mi1[MT], mi2[MT];
    __shared__ int   sidx[MT];

    const int tid   = threadIdx.x;
    const int warp  = tid >> 5;
    const int lane  = tid & 31;
    const int g     = lane >> 2;       // row within m16 tile
    const int T     = lane & 3;        // thread in quad
    const int tile  = warp & 3;        // which 16-latent tile
    const int khalf = warp >> 2;       // which 512-code half
    const int lbase = blockIdx.x * MT;

    // stage ||e||^2
    #pragma unroll
    for (int i = 0; i < KQ / THREADS; i++)
        cs[tid + i * THREADS] = g_c[tid + i * THREADS];

    // Stage chunk ch (both halves, hi+lo) via cp.async: 1024 16B moves.
    auto stage = [&](int ch, int buf) {
        #pragma unroll
        for (int i = 0; i < 4; i++) {
            int u    = tid + i * THREADS;      // 0..1023
            int seg  = u & 7;
            int row  = (u >> 3) & 31;
            int tab  = (u >> 8) & 1;
            int half = u >> 9;
            const __half* src = tab ? g_elo : g_ehi;
            cp16(&sB[buf][half][tab][row * SROW + seg * 8],
                 &src[(size_t)(half * KHALF + ch * CHK + row) * EDIM + seg * 8]);
        }
        asm volatile("cp.async.commit_group;" ::: "memory");
    };

    stage(0, 0);

    // ldmatrix per-lane base offsets (verified mapping from R8, rel_err 0.0):
    // lanes 0-7: rows g (n 0..7) k-lo; 8-15: same rows k+8; 16-23: rows +8 k-lo;
    // 24-31: rows +8 k+8.  h0,h1 -> n-tile j=0; h2,h3 -> j=1.
    const unsigned lane_off =
        (unsigned)(((lane & 7) + ((lane >> 4) << 3)) * (SROW * 2)
                   + ((lane >> 3) & 1) * 16);
    const unsigned sm_hi0 =
        (unsigned)__cvta_generic_to_shared(&sB[0][khalf][0][0]) + lane_off;
    const unsigned sm_lo0 =
        (unsigned)__cvta_generic_to_shared(&sB[0][khalf][1][0]) + lane_off;
    const unsigned BUFSTRIDE = 2u * 2u * CHK * SROW * 2u;   // bytes per buf

    // A fragments: rows r0 = tile*16+g, r1 = r0+8 of (-2x), hi/lo split.
    unsigned ahi[4][4], alo[4][4];
    {
        const float* xr0 = x + (size_t)(lbase + tile * 16 + g) * EDIM;
        const float* xr1 = xr0 + 8 * EDIM;
        #pragma unroll
        for (int ks = 0; ks < 4; ks++) {
            int c0 = 16 * ks + 2 * T;
            float2 v;
            v = *reinterpret_cast<const float2*>(xr0 + c0);
            ahi[ks][0] = packsplit(-2.f * v.x, -2.f * v.y, alo[ks][0]);
            v = *reinterpret_cast<const float2*>(xr1 + c0);
            ahi[ks][1] = packsplit(-2.f * v.x, -2.f * v.y, alo[ks][1]);
            v = *reinterpret_cast<const float2*>(xr0 + c0 + 8);
            ahi[ks][2] = packsplit(-2.f * v.x, -2.f * v.y, alo[ks][2]);
            v = *reinterpret_cast<const float2*>(xr1 + c0 + 8);
            ahi[ks][3] = packsplit(-2.f * v.x, -2.f * v.y, alo[ks][3]);
        }
    }

    Top2 tp[2];
    tp[0].b1 = tp[0].b2 = 3.4e38f; tp[0].i1 = tp[0].i2 = 0;
    tp[1].b1 = tp[1].b2 = 3.4e38f; tp[1].i1 = tp[1].i2 = 0;

    asm volatile("cp.async.wait_group 0;" ::: "memory");
    __syncthreads();

    int buf = 0;
    #pragma unroll 1
    for (int ch = 0; ch < NCHUNK; ch++) {
        if (ch + 1 < NCHUNK) stage(ch + 1, buf ^ 1);   // overlap next stage

        const unsigned base_hi = sm_hi0 + (unsigned)buf * BUFSTRIDE;
        const unsigned base_lo = sm_lo0 + (unsigned)buf * BUFSTRIDE;
        const int c0 = khalf * KHALF + ch * CHK;

        #pragma unroll
        for (int nb = 0; nb < CHK; nb += 16) {
            float dhh[2][4] = {{0,0,0,0},{0,0,0,0}};
            float dhl[2][4] = {{0,0,0,0},{0,0,0,0}};
            float dlh[2][4] = {{0,0,0,0},{0,0,0,0}};
            const unsigned nboff = (unsigned)(nb * SROW * 2);
            #pragma unroll
            for (int kh = 0; kh < 2; kh++) {
                // Batch ALL 4 LDSM first (MLP=4), then 12 MMAs.
                unsigned h0[4], h1[4], l0[4], l1[4];
                unsigned ko = (unsigned)(kh * 64);
                ldsm4(h0[0], h0[1], h0[2], h0[3], base_hi + nboff + ko);
                ldsm4(h1[0], h1[1], h1[2], h1[3], base_hi + nboff + ko + 32);
                ldsm4(l0[0], l0[1], l0[2], l0[3], base_lo + nboff + ko);
                ldsm4(l1[0], l1[1], l1[2], l1[3], base_lo + nboff + ko + 32);
                int ks = 2 * kh;
                #pragma unroll
                for (int j = 0; j < 2; j++) {
                    // per-accumulator ks order 0,1,2,3 — identical to R7
                    mma16816(dhh[j], ahi[ks],     h0[2*j], h0[2*j+1]);
                    mma16816(dhl[j], ahi[ks],     l0[2*j], l0[2*j+1]);
                    mma16816(dlh[j], alo[ks],     h0[2*j], h0[2*j+1]);
                    mma16816(dhh[j], ahi[ks + 1], h1[2*j], h1[2*j+1]);
                    mma16816(dhl[j], ahi[ks + 1], l1[2*j], l1[2*j+1]);
                    mma16816(dlh[j], alo[ks + 1], h1[2*j], h1[2*j+1]);
                }
            }
            #pragma unroll
            for (int j = 0; j < 2; j++) {
                int col = c0 + nb + 8 * j + 2 * T;
                float e0 = cs[col], e1 = cs[col + 1];
                upd(tp[0], e0 + (dhh[j][0] + dhl[j][0] + dlh[j][0]), col);
                upd(tp[0], e1 + (dhh[j][1] + dhl[j][1] + dlh[j][1]), col + 1);
                upd(tp[1], e0 + (dhh[j][2] + dhl[j][2] + dlh[j][2]), col);
                upd(tp[1], e1 + (dhh[j][3] + dhl[j][3] + dlh[j][3]), col + 1);
            }
        }

        asm volatile("cp.async.wait_group 0;" ::: "memory");
        __syncthreads();
        buf ^= 1;
    }

    // Reduce across the 4 lanes of each quad (xor 1, 2 stay in-quad).
    #pragma unroll
    for (int s = 0; s < 2; s++) {
        #pragma unroll
        for (int m = 1; m < 4; m <<= 1) {
            float ob1 = __shfl_xor_sync(0xffffffffu, tp[s].b1, m);
            float ob2 = __shfl_xor_sync(0xffffffffu, tp[s].b2, m);
            int   oi1 = __shfl_xor_sync(0xffffffffu, tp[s].i1, m);
            int   oi2 = __shfl_xor_sync(0xffffffffu, tp[s].i2, m);
            bool of = (ob1 < tp[s].b1) || (ob1 == tp[s].b1 && oi1 < tp[s].i1);
            if (of) {
                bool t2 = (tp[s].b1 < ob2) || (tp[s].b1 == ob2 && tp[s].i1 < oi2);
                tp[s].b2 = t2 ? tp[s].b1 : ob2;
                tp[s].i2 = t2 ? tp[s].i1 : oi2;
                tp[s].b1 = ob1; tp[s].i1 = oi1;
            } else {
                bool t2 = (ob1 < tp[s].b2) || (ob1 == tp[s].b2 && oi1 < tp[s].i2);
                if (t2) { tp[s].b2 = ob1; tp[s].i2 = oi1; }
            }
        }
    }

    // k-half merge: khalf1 publishes, khalf0 merges (half0 idx < half1 idx,
    // strict < keeps first-min semantics).
    if (khalf == 1 && T == 0) {
        #pragma unroll
        for (int s = 0; s < 2; s++) {
            int lr = tile * 16 + g + 8 * s;
            mb1[lr] = tp[s].b1; mi1[lr] = tp[s].i1;
            mb2[lr] = tp[s].b2; mi2[lr] = tp[s].i2;
        }
    }
    __syncthreads();

    if (khalf == 0 && T == 0) {
        #pragma unroll
        for (int s = 0; s < 2; s++) {
            int lr = tile * 16 + g + 8 * s;
            float ob1 = mb1[lr], ob2 = mb2[lr];
            int   oi1 = mi1[lr], oi2 = mi2[lr];
            if (ob1 < tp[s].b1) {
                bool t2 = (tp[s].b1 <= ob2);
                tp[s].b2 = t2 ? tp[s].b1 : ob2;
                tp[s].i2 = t2 ? tp[s].i1 : oi2;
                tp[s].b1 = ob1; tp[s].i1 = oi1;
            } else if (ob1 < tp[s].b2) {
                tp[s].b2 = ob1; tp[s].i2 = oi1;
            }

            int win = tp[s].i1;
            if (tp[s].b2 - tp[s].b1 < 5e-3f) {
                // exact fp32 recheck of the two candidates
                const float* xr  = x   + (size_t)(lbase + lr) * EDIM;
                const float* e1r = emb + (size_t)tp[s].i1 * EDIM;
                const float* e2r = emb + (size_t)tp[s].i2 * EDIM;
                float d1 = 0.f, d2 = 0.f;
                #pragma unroll 8
                for (int e = 0; e < EDIM; e++) {
                    float xv = xr[e];
                    d1 = fmaf(xv, e1r[e], d1);
                    d2 = fmaf(xv, e2r[e], d2);
                }
                float s1 = fmaf(-2.f, d1, cs[tp[s].i1]);
                float s2 = fmaf(-2.f, d2, cs[tp[s].i2]);
                if (s2 < s1 || (s2 == s1 && tp[s].i2 < tp[s].i1)) win = tp[s].i2;
            }
            sidx[lr] = win;
        }
    }
    __syncthreads();

    // Coalesced epilogue: out = [x | quantized | z_hat | indices], fp32.
    const size_t LE4 = (size_t)L_TOTAL * (EDIM / 4);
    const float4* x4  = reinterpret_cast<const float4*>(x);
    const float4* e4p = reinterpret_cast<const float4*>(emb);
    float4* out4 = reinterpret_cast<float4*>(out);
    #pragma unroll
    for (int i = 0; i < (MT * EDIM / 4) / THREADS; i++) {
        int idx = tid + i * THREADS;
        int l = idx >> 4, c4 = idx & 15;
        size_t goff = (size_t)(lbase + l) * 16 + c4;
        float4 xv = x4[goff];
        float4 qv = e4p[(size_t)sidx[l] * 16 + c4];
        out4[goff] = xv;
        out4[LE4 + goff] = qv;
        float4 zh;
        zh.x = (xv.x + qv.x) - xv.x;
        zh.y = (xv.y + qv.y) - xv.y;
        zh.z = (xv.z + qv.z) - xv.z;
        zh.w = (xv.w + qv.w) - xv.w;
        out4[2 * LE4 + goff] = zh;
    }
    if (tid < MT)
        out[3 * (size_t)L_TOTAL * EDIM + lbase + tid] = (float)sidx[tid];
}

extern "C" void kernel_launch(void* const* d_in, const int* in_sizes, int n_in,
                              void* d_out, int out_size) {
    const float* x   = (const float*)d_in[0];
    const float* emb = (const float*)d_in[1];
    float* out       = (float*)d_out;

    vq_prep_kernel<<<64, 128>>>(emb);
    vq_mma_kernel<<<L_TOTAL / MT, THREADS>>>(x, emb, out);
}

// round 11
// speedup vs baseline: 1.9582x; 1.2286x over previous
#include <cuda_runtime.h>
#include <cuda_fp16.h>

#define L_TOTAL 32768
#define KQ      1024
#define EDIM    64
#define MT      32             // latents per CTA (2 tiles x 16)
#define KHALF   512            // codes per k-split half
#define CHK     16             // codes per staged chunk per half
#define NCHUNK  (KHALF / CHK)  // 32
#define SROW    72             // padded smem row stride (halves) -> conflict-free
#define THREADS 128

// scratch tables (no cudaMalloc allowed)
__device__ float  g_c[KQ];             // ||e_k||^2 (fp32)
__device__ __half g_ehi[KQ * EDIM];    // fp16-rounded embeddings [k][e]
__device__ __half g_elo[KQ * EDIM];    // residual

__device__ __forceinline__ void mma16816(float* d, const unsigned* a,
                                         unsigned b0, unsigned b1) {
    asm volatile(
        "mma.sync.aligned.m16n8k16.row.col.f32.f16.f16.f32 "
        "{%0,%1,%2,%3}, {%4,%5,%6,%7}, {%8,%9}, {%0,%1,%2,%3};"
        : "+f"(d[0]), "+f"(d[1]), "+f"(d[2]), "+f"(d[3])
        : "r"(a[0]), "r"(a[1]), "r"(a[2]), "r"(a[3]), "r"(b0), "r"(b1));
}

__device__ __forceinline__ void ldsm4(unsigned& r0, unsigned& r1,
                                      unsigned& r2, unsigned& r3,
                                      unsigned addr) {
    asm volatile("ldmatrix.sync.aligned.m8n8.x4.shared.b16 {%0,%1,%2,%3}, [%4];"
                 : "=r"(r0), "=r"(r1), "=r"(r2), "=r"(r3) : "r"(addr));
}

__device__ __forceinline__ unsigned packsplit(float a, float b, unsigned& lo) {
    __half ha = __float2half_rn(a), hb = __float2half_rn(b);
    float la = a - __half2float(ha), lb = b - __half2float(hb);
    __half2 H = __halves2half2(ha, hb);
    __half2 L = __halves2half2(__float2half_rn(la), __float2half_rn(lb));
    lo = *reinterpret_cast<unsigned*>(&L);
    return *reinterpret_cast<unsigned*>(&H);
}

__device__ __forceinline__ unsigned packhi(float a, float b) {
    __half2 H = __halves2half2(__float2half_rn(a), __float2half_rn(b));
    return *reinterpret_cast<unsigned*>(&H);
}

__device__ __forceinline__ void cp16(void* dst_smem, const void* src) {
    unsigned d = (unsigned)__cvta_generic_to_shared(dst_smem);
    asm volatile("cp.async.cg.shared.global [%0], [%1], 16;"
                 :: "r"(d), "l"(src) : "memory");
}

// Parallel prep: 8 threads per code row. ||e||^2 via 8-lane shfl tree.
__global__ void vq_prep_kernel(const float* __restrict__ emb) {
    int t   = blockIdx.x * blockDim.x + threadIdx.x;  // 0..8191
    int k   = t >> 3;
    int seg = t & 7;
    const float4* p = reinterpret_cast<const float4*>(emb + k * EDIM + seg * 8);
    float4 v0 = p[0], v1 = p[1];
    float s = v0.x * v0.x + v0.y * v0.y + v0.z * v0.z + v0.w * v0.w
            + v1.x * v1.x + v1.y * v1.y + v1.z * v1.z + v1.w * v1.w;
    uint4 H, L;
    H.x = packsplit(v0.x, v0.y, L.x);
    H.y = packsplit(v0.z, v0.w, L.y);
    H.z = packsplit(v1.x, v1.y, L.z);
    H.w = packsplit(v1.z, v1.w, L.w);
    *reinterpret_cast<uint4*>(&g_ehi[k * EDIM + seg * 8]) = H;
    *reinterpret_cast<uint4*>(&g_elo[k * EDIM + seg * 8]) = L;
    s += __shfl_xor_sync(0xffffffffu, s, 1);
    s += __shfl_xor_sync(0xffffffffu, s, 2);
    s += __shfl_xor_sync(0xffffffffu, s, 4);
    if (seg == 0) g_c[k] = s;
}

struct Top2 { float b1, b2; int i1, i2; };

__device__ __forceinline__ void upd(Top2& t, float s, int c) {
    if (s < t.b1)      { t.b2 = t.b1; t.i2 = t.i1; t.b1 = s; t.i1 = c; }
    else if (s < t.b2) { t.b2 = s; t.i2 = c; }
}

__global__ void __launch_bounds__(THREADS, 7)
vq_mma_kernel(const float* __restrict__ x,
              const float* __restrict__ emb,
              float* __restrict__ out) {
    // [buf][half][tab(hi/lo)] double-buffered code chunks
    __shared__ __align__(16) __half sB[2][2][2][CHK * SROW];
    __shared__ float cs[KQ];
    __shared__ float mb1[MT], mb2[MT];
    __shared__ int   mi1[MT], mi2[MT];
    __shared__ int   sidx[MT];

    const int tid   = threadIdx.x;
    const int warp  = tid >> 5;
    const int lane  = tid & 31;
    const int g     = lane >> 2;       // row within m16 tile
    const int T     = lane & 3;        // thread in quad
    const int tile  = warp & 1;        // which 16-latent tile
    const int khalf = warp >> 1;       // which 512-code half
    const int lbase = blockIdx.x * MT;

    // stage ||e||^2
    #pragma unroll
    for (int i = 0; i < KQ / THREADS; i++)
        cs[tid + i * THREADS] = g_c[tid + i * THREADS];

    // Stage chunk ch (both halves, hi+lo) via cp.async: 512 16B moves.
    auto stage = [&](int ch, int buf) {
        #pragma unroll
        for (int i = 0; i < 4; i++) {
            int u    = tid + i * THREADS;      // 0..511
            int seg  = u & 7;
            int row  = (u >> 3) & 15;
            int tab  = (u >> 7) & 1;
            int half = u >> 8;
            const __half* src = tab ? g_elo : g_ehi;
            cp16(&sB[buf][half][tab][row * SROW + seg * 8],
                 &src[(size_t)(half * KHALF + ch * CHK + row) * EDIM + seg * 8]);
        }
        asm volatile("cp.async.commit_group;" ::: "memory");
    };

    stage(0, 0);

    // ldmatrix per-lane base offsets (verified mapping, rel_err 0.0 in R10):
    // lanes 0-7: rows 0-7 k-lo; 8-15: k+8; 16-23: rows 8-15 k-lo; 24-31: k+8.
    const unsigned lane_off =
        (unsigned)(((lane & 7) + ((lane >> 4) << 3)) * (SROW * 2)
                   + ((lane >> 3) & 1) * 16);
    const unsigned sm_hi0 =
        (unsigned)__cvta_generic_to_shared(&sB[0][khalf][0][0]) + lane_off;
    const unsigned sm_lo0 =
        (unsigned)__cvta_generic_to_shared(&sB[0][khalf][1][0]) + lane_off;
    const unsigned BUFSTRIDE = 2u * 2u * CHK * SROW * 2u;   // bytes per buf

    // A fragments: rows r0 = tile*16+g, r1 = r0+8 of (-2x), fp16-hi only
    // (the x_lo x e pass is dropped; the widened exact-recheck guard absorbs it).
    unsigned ahi[4][4];
    {
        const float* xr0 = x + (size_t)(lbase + tile * 16 + g) * EDIM;
        const float* xr1 = xr0 + 8 * EDIM;
        #pragma unroll
        for (int ks = 0; ks < 4; ks++) {
            int c0 = 16 * ks + 2 * T;
            float2 v;
            v = *reinterpret_cast<const float2*>(xr0 + c0);
            ahi[ks][0] = packhi(-2.f * v.x, -2.f * v.y);
            v = *reinterpret_cast<const float2*>(xr1 + c0);
            ahi[ks][1] = packhi(-2.f * v.x, -2.f * v.y);
            v = *reinterpret_cast<const float2*>(xr0 + c0 + 8);
            ahi[ks][2] = packhi(-2.f * v.x, -2.f * v.y);
            v = *reinterpret_cast<const float2*>(xr1 + c0 + 8);
            ahi[ks][3] = packhi(-2.f * v.x, -2.f * v.y);
        }
    }

    Top2 tp[2];
    tp[0].b1 = tp[0].b2 = 3.4e38f; tp[0].i1 = tp[0].i2 = 0;
    tp[1].b1 = tp[1].b2 = 3.4e38f; tp[1].i1 = tp[1].i2 = 0;

    asm volatile("cp.async.wait_group 0;" ::: "memory");
    __syncthreads();

    int buf = 0;
    #pragma unroll 1
    for (int ch = 0; ch < NCHUNK; ch++) {
        if (ch + 1 < NCHUNK) stage(ch + 1, buf ^ 1);   // overlap next stage

        const unsigned base_hi = sm_hi0 + (unsigned)buf * BUFSTRIDE;
        const unsigned base_lo = sm_lo0 + (unsigned)buf * BUFSTRIDE;
        const int c0 = khalf * KHALF + ch * CHK;

        // CHK=16 -> exactly one n16-tile per chunk.
        float dhh[2][4] = {{0,0,0,0},{0,0,0,0}};
        float dhl[2][4] = {{0,0,0,0},{0,0,0,0}};
        #pragma unroll
        for (int kh = 0; kh < 2; kh++) {
            // Batch ALL 4 LDSM first (MLP=4), then 8 MMAs.
            unsigned h0[4], h1[4], l0[4], l1[4];
            unsigned ko = (unsigned)(kh * 64);
            ldsm4(h0[0], h0[1], h0[2], h0[3], base_hi + ko);
            ldsm4(h1[0], h1[1], h1[2], h1[3], base_hi + ko + 32);
            ldsm4(l0[0], l0[1], l0[2], l0[3], base_lo + ko);
            ldsm4(l1[0], l1[1], l1[2], l1[3], base_lo + ko + 32);
            int ks = 2 * kh;
            #pragma unroll
            for (int j = 0; j < 2; j++) {
                mma16816(dhh[j], ahi[ks],     h0[2*j], h0[2*j+1]);  // hi*hi
                mma16816(dhl[j], ahi[ks],     l0[2*j], l0[2*j+1]);  // hi*lo
                mma16816(dhh[j], ahi[ks + 1], h1[2*j], h1[2*j+1]);
                mma16816(dhl[j], ahi[ks + 1], l1[2*j], l1[2*j+1]);
            }
        }
        #pragma unroll
        for (int j = 0; j < 2; j++) {
            int col = c0 + 8 * j + 2 * T;
            float e0 = cs[col], e1 = cs[col + 1];
            upd(tp[0], e0 + (dhh[j][0] + dhl[j][0]), col);
            upd(tp[0], e1 + (dhh[j][1] + dhl[j][1]), col + 1);
            upd(tp[1], e0 + (dhh[j][2] + dhl[j][2]), col);
            upd(tp[1], e1 + (dhh[j][3] + dhl[j][3]), col + 1);
        }

        asm volatile("cp.async.wait_group 0;" ::: "memory");
        __syncthreads();
        buf ^= 1;
    }

    // Reduce across the 4 lanes of each quad (xor 1, 2 stay in-quad).
    #pragma unroll
    for (int s = 0; s < 2; s++) {
        #pragma unroll
        for (int m = 1; m < 4; m <<= 1) {
            float ob1 = __shfl_xor_sync(0xffffffffu, tp[s].b1, m);
            float ob2 = __shfl_xor_sync(0xffffffffu, tp[s].b2, m);
            int   oi1 = __shfl_xor_sync(0xffffffffu, tp[s].i1, m);
            int   oi2 = __shfl_xor_sync(0xffffffffu, tp[s].i2, m);
            bool of = (ob1 < tp[s].b1) || (ob1 == tp[s].b1 && oi1 < tp[s].i1);
            if (of) {
                bool t2 = (tp[s].b1 < ob2) || (tp[s].b1 == ob2 && tp[s].i1 < oi2);
                tp[s].b2 = t2 ? tp[s].b1 : ob2;
                tp[s].i2 = t2 ? tp[s].i1 : oi2;
                tp[s].b1 = ob1; tp[s].i1 = oi1;
            } else {
                bool t2 = (ob1 < tp[s].b2) || (ob1 == tp[s].b2 && oi1 < tp[s].i2);
                if (t2) { tp[s].b2 = ob1; tp[s].i2 = oi1; }
            }
        }
    }

    // k-half merge: khalf1 publishes, khalf0 merges (half0 idx < half1 idx,
    // strict < keeps first-min semantics).
    if (khalf == 1 && T == 0) {
        #pragma unroll
        for (int s = 0; s < 2; s++) {
            int lr = tile * 16 + g + 8 * s;
            mb1[lr] = tp[s].b1; mi1[lr] = tp[s].i1;
            mb2[lr] = tp[s].b2; mi2[lr] = tp[s].i2;
        }
    }
    __syncthreads();

    if (khalf == 0 && T == 0) {
        #pragma unroll
        for (int s = 0; s < 2; s++) {
            int lr = tile * 16 + g + 8 * s;
            float ob1 = mb1[lr], ob2 = mb2[lr];
            int   oi1 = mi1[lr], oi2 = mi2[lr];
            if (ob1 < tp[s].b1) {
                bool t2 = (tp[s].b1 <= ob2);
                tp[s].b2 = t2 ? tp[s].b1 : ob2;
                tp[s].i2 = t2 ? tp[s].i1 : oi2;
                tp[s].b1 = ob1; tp[s].i1 = oi1;
            } else if (ob1 < tp[s].b2) {
                tp[s].b2 = ob1; tp[s].i2 = oi1;
            }

            int win = tp[s].i1;
            // Widened guard (2-pass split): exact fp32 recheck when close.
            if (tp[s].b2 - tp[s].b1 < 3e-2f) {
                const float* xr  = x   + (size_t)(lbase + lr) * EDIM;
                const float* e1r = emb + (size_t)tp[s].i1 * EDIM;
                const float* e2r = emb + (size_t)tp[s].i2 * EDIM;
                float d1 = 0.f, d2 = 0.f;
                #pragma unroll 8
                for (int e = 0; e < EDIM; e++) {
                    float xv = xr[e];
                    d1 = fmaf(xv, e1r[e], d1);
                    d2 = fmaf(xv, e2r[e], d2);
                }
                float s1 = fmaf(-2.f, d1, cs[tp[s].i1]);
                float s2 = fmaf(-2.f, d2, cs[tp[s].i2]);
                if (s2 < s1 || (s2 == s1 && tp[s].i2 < tp[s].i1)) win = tp[s].i2;
            }
            sidx[lr] = win;
        }
    }
    __syncthreads();

    // Coalesced epilogue: out = [x | quantized | z_hat | indices], fp32.
    const size_t LE4 = (size_t)L_TOTAL * (EDIM / 4);
    const float4* x4  = reinterpret_cast<const float4*>(x);
    const float4* e4p = reinterpret_cast<const float4*>(emb);
    float4* out4 = reinterpret_cast<float4*>(out);
    #pragma unroll
    for (int i = 0; i < (MT * EDIM / 4) / THREADS; i++) {
        int idx = tid + i * THREADS;
        int l = idx >> 4, c4 = idx & 15;
        size_t goff = (size_t)(lbase + l) * 16 + c4;
        float4 xv = x4[goff];
        float4 qv = e4p[(size_t)sidx[l] * 16 + c4];
        out4[goff] = xv;
        out4[LE4 + goff] = qv;
        float4 zh;
        zh.x = (xv.x + qv.x) - xv.x;
        zh.y = (xv.y + qv.y) - xv.y;
        zh.z = (xv.z + qv.z) - xv.z;
        zh.w = (xv.w + qv.w) - xv.w;
        out4[2 * LE4 + goff] = zh;
    }
    if (tid < MT)
        out[3 * (size_t)L_TOTAL * EDIM + lbase + tid] = (float)sidx[tid];
}

extern "C" void kernel_launch(void* const* d_in, const int* in_sizes, int n_in,
                              void* d_out, int out_size) {
    const float* x   = (const float*)d_in[0];
    const float* emb = (const float*)d_in[1];
    float* out       = (float*)d_out;

    vq_prep_kernel<<<64, 128>>>(emb);
    vq_mma_kernel<<<L_TOTAL / MT, THREADS>>>(x, emb, out);
}